// round 4
// baseline (speedup 1.0000x reference)
#include <cuda_runtime.h>
#include <math.h>

#define DM   1024
#define NH   16
#define HD   64
#define BATCH 2
#define SEQ  2048
#define MTOT (BATCH*SEQ)

// Scratch (allocation-free rule: __device__ globals)
__device__ float g_Q[MTOT*DM];
__device__ float g_K[MTOT*DM];
__device__ float g_V[MTOT*DM];
__device__ float g_C[MTOT*DM];

// ---------------------------------------------------------------------------
// NT-GEMM: C[m][n] = sum_k A[m][k] * B[n][k]
// A: [M,K] row-major, B: [N,K] row-major (nn.Linear weight), C: [M,N]
// 128x128 tile, BK=16, 256 threads, 8x8 per thread.
// ---------------------------------------------------------------------------
__global__ __launch_bounds__(256) void gemm_nt_kernel(
    const float* __restrict__ A, const float* __restrict__ B,
    float* __restrict__ C, int M, int N, int K)
{
    const int BM = 128, BN = 128, BK = 16;
    __shared__ float As[BK][BM + 4];
    __shared__ float Bs[BK][BN + 4];

    const int tid = threadIdx.x;
    const int tr  = tid >> 4;        // 0..15
    const int tc  = tid & 15;        // 0..15
    const int m0  = blockIdx.y * BM;
    const int n0  = blockIdx.x * BN;

    const int lrow = tid >> 2;        // 0..63
    const int lcol = (tid & 3) << 2;  // 0,4,8,12

    float acc[8][8];
#pragma unroll
    for (int i = 0; i < 8; i++)
#pragma unroll
        for (int j = 0; j < 8; j++) acc[i][j] = 0.0f;

    for (int k0 = 0; k0 < K; k0 += BK) {
#pragma unroll
        for (int r = 0; r < 2; r++) {
            int row = lrow + r * 64;
            float4 va = *(const float4*)&A[(size_t)(m0 + row) * K + k0 + lcol];
            As[lcol + 0][row] = va.x; As[lcol + 1][row] = va.y;
            As[lcol + 2][row] = va.z; As[lcol + 3][row] = va.w;
            float4 vb = *(const float4*)&B[(size_t)(n0 + row) * K + k0 + lcol];
            Bs[lcol + 0][row] = vb.x; Bs[lcol + 1][row] = vb.y;
            Bs[lcol + 2][row] = vb.z; Bs[lcol + 3][row] = vb.w;
        }
        __syncthreads();

#pragma unroll
        for (int k = 0; k < BK; k++) {
            float a[8], b[8];
            *(float4*)&a[0] = *(float4*)&As[k][tr * 8];
            *(float4*)&a[4] = *(float4*)&As[k][tr * 8 + 4];
            *(float4*)&b[0] = *(float4*)&Bs[k][tc * 8];
            *(float4*)&b[4] = *(float4*)&Bs[k][tc * 8 + 4];
#pragma unroll
            for (int i = 0; i < 8; i++)
#pragma unroll
                for (int j = 0; j < 8; j++)
                    acc[i][j] += a[i] * b[j];
        }
        __syncthreads();
    }

#pragma unroll
    for (int i = 0; i < 8; i++) {
        float* crow = &C[(size_t)(m0 + tr * 8 + i) * N + n0 + tc * 8];
        float4 v0 = make_float4(acc[i][0], acc[i][1], acc[i][2], acc[i][3]);
        float4 v1 = make_float4(acc[i][4], acc[i][5], acc[i][6], acc[i][7]);
        *(float4*)&crow[0] = v0;
        *(float4*)&crow[4] = v1;
    }
}

// ---------------------------------------------------------------------------
// Flash attention (fp32, online softmax)
// Grid: (SEQ/BQ, BATCH*NH). Block: 256 threads.
// Q/K/V/ctx are [MTOT, DM] with head slices at h*HD.
// ---------------------------------------------------------------------------
#define BQ   128
#define BKV  128
#define QP   (BQ + 4)     // 132
#define KP   (BKV + 4)    // 132
#define VP   (HD + 4)     // 68
#define PP   (BQ + 4)     // 132
#define SMEM_FLOATS (HD*QP + HD*KP + BKV*VP + BKV*PP)
#define SMEM_BYTES  (SMEM_FLOATS * 4)

__global__ __launch_bounds__(256) void flash_attn_kernel(
    const float* __restrict__ Q, const float* __restrict__ K,
    const float* __restrict__ V, float* __restrict__ O)
{
    extern __shared__ float sm[];
    float* Qt = sm;                 // [HD][QP]   Qt[k][q]
    float* Kt = Qt + HD * QP;       // [HD][KP]   Kt[k][kv]
    float* Vs = Kt + HD * KP;       // [BKV][VP]  Vs[kv][c]
    float* Pt = Vs + BKV * VP;      // [BKV][PP]  Pt[kv][q]

    const int tid = threadIdx.x;
    const int tr  = tid >> 4;       // 0..15 (q row group)
    const int tc  = tid & 15;       // 0..15
    const int bh  = blockIdx.y;     // 0..31
    const int b   = bh >> 4;
    const int h   = bh & 15;
    const int q0  = blockIdx.x * BQ;
    const long qbase = (long)(b * SEQ + q0);
    const long kvbase0 = (long)(b * SEQ);
    const int hb = h * HD;
    const float scale = 0.03125f;   // 1/sqrt(1024)

    // ---- load Q tile transposed: Qt[k][q] ----
    for (int idx = tid; idx < BQ * (HD / 4); idx += 256) {
        int row = idx >> 4;         // 0..127
        int c4  = (idx & 15) << 2;  // 0,4,...,60
        float4 v = *(const float4*)&Q[(qbase + row) * DM + hb + c4];
        Qt[(c4 + 0) * QP + row] = v.x;
        Qt[(c4 + 1) * QP + row] = v.y;
        Qt[(c4 + 2) * QP + row] = v.z;
        Qt[(c4 + 3) * QP + row] = v.w;
    }

    float m_i[8], l_i[8], o[8][4];
#pragma unroll
    for (int i = 0; i < 8; i++) {
        m_i[i] = -1e30f; l_i[i] = 0.0f;
#pragma unroll
        for (int c = 0; c < 4; c++) o[i][c] = 0.0f;
    }
    __syncthreads();

    for (int kb = 0; kb < SEQ / BKV; kb++) {
        // ---- load K (transposed) and V tiles ----
        const long kvr = kvbase0 + kb * BKV;
        for (int idx = tid; idx < BKV * (HD / 4); idx += 256) {
            int row = idx >> 4;
            int c4  = (idx & 15) << 2;
            float4 vk = *(const float4*)&K[(kvr + row) * DM + hb + c4];
            Kt[(c4 + 0) * KP + row] = vk.x;
            Kt[(c4 + 1) * KP + row] = vk.y;
            Kt[(c4 + 2) * KP + row] = vk.z;
            Kt[(c4 + 3) * KP + row] = vk.w;
            float4 vv = *(const float4*)&V[(kvr + row) * DM + hb + c4];
            *(float4*)&Vs[row * VP + c4] = vv;
        }
        __syncthreads();

        // ---- S = Q K^T (8x8 per thread) ----
        float s_[8][8];
#pragma unroll
        for (int i = 0; i < 8; i++)
#pragma unroll
            for (int j = 0; j < 8; j++) s_[i][j] = 0.0f;

#pragma unroll 4
        for (int k = 0; k < HD; k++) {
            float a[8], bq[8];
            *(float4*)&a[0]  = *(float4*)&Qt[k * QP + tr * 8];
            *(float4*)&a[4]  = *(float4*)&Qt[k * QP + tr * 8 + 4];
            *(float4*)&bq[0] = *(float4*)&Kt[k * KP + tc * 8];
            *(float4*)&bq[4] = *(float4*)&Kt[k * KP + tc * 8 + 4];
#pragma unroll
            for (int i = 0; i < 8; i++)
#pragma unroll
                for (int j = 0; j < 8; j++)
                    s_[i][j] += a[i] * bq[j];
        }

        // ---- online softmax (row groups of 16 lanes) ----
#pragma unroll
        for (int i = 0; i < 8; i++) {
            float rm = -1e30f;
#pragma unroll
            for (int j = 0; j < 8; j++) {
                s_[i][j] *= scale;
                rm = fmaxf(rm, s_[i][j]);
            }
#pragma unroll
            for (int off = 8; off >= 1; off >>= 1)
                rm = fmaxf(rm, __shfl_xor_sync(0xffffffffu, rm, off, 16));

            float m_new = fmaxf(m_i[i], rm);
            float corr  = __expf(m_i[i] - m_new);
            float rs = 0.0f;
#pragma unroll
            for (int j = 0; j < 8; j++) {
                float p = __expf(s_[i][j] - m_new);
                Pt[(tc * 8 + j) * PP + tr * 8 + i] = p;
                rs += p;
            }
#pragma unroll
            for (int off = 8; off >= 1; off >>= 1)
                rs += __shfl_xor_sync(0xffffffffu, rs, off, 16);

            l_i[i] = l_i[i] * corr + rs;
            m_i[i] = m_new;
#pragma unroll
            for (int c = 0; c < 4; c++) o[i][c] *= corr;
        }
        __syncthreads();

        // ---- O += P V (8 rows x 4 cols per thread) ----
#pragma unroll 4
        for (int j = 0; j < BKV; j++) {
            float a[8];
            *(float4*)&a[0] = *(float4*)&Pt[j * PP + tr * 8];
            *(float4*)&a[4] = *(float4*)&Pt[j * PP + tr * 8 + 4];
            float4 bv = *(const float4*)&Vs[j * VP + tc * 4];
#pragma unroll
            for (int i = 0; i < 8; i++) {
                o[i][0] += a[i] * bv.x;
                o[i][1] += a[i] * bv.y;
                o[i][2] += a[i] * bv.z;
                o[i][3] += a[i] * bv.w;
            }
        }
        __syncthreads();
    }

    // ---- normalize + write ctx ----
#pragma unroll
    for (int i = 0; i < 8; i++) {
        float inv = 1.0f / l_i[i];
        float4 v = make_float4(o[i][0] * inv, o[i][1] * inv,
                               o[i][2] * inv, o[i][3] * inv);
        *(float4*)&O[(qbase + tr * 8 + i) * DM + hb + tc * 4] = v;
    }
}

// ---------------------------------------------------------------------------
extern "C" void kernel_launch(void* const* d_in, const int* in_sizes, int n_in,
                              void* d_out, int out_size)
{
    const float* x  = (const float*)d_in[0];
    const float* Wq = (const float*)d_in[1];
    const float* Wk = (const float*)d_in[2];
    const float* Wv = (const float*)d_in[3];
    const float* Wo = (const float*)d_in[4];
    float* out = (float*)d_out;

    float *Qp, *Kp, *Vp, *Cp;
    cudaGetSymbolAddress((void**)&Qp, g_Q);
    cudaGetSymbolAddress((void**)&Kp, g_K);
    cudaGetSymbolAddress((void**)&Vp, g_V);
    cudaGetSymbolAddress((void**)&Cp, g_C);

    dim3 gg(DM / 128, MTOT / 128);   // (8, 32)
    gemm_nt_kernel<<<gg, 256>>>(x, Wq, Qp, MTOT, DM, DM);
    gemm_nt_kernel<<<gg, 256>>>(x, Wk, Kp, MTOT, DM, DM);
    gemm_nt_kernel<<<gg, 256>>>(x, Wv, Vp, MTOT, DM, DM);

    cudaFuncSetAttribute(flash_attn_kernel,
                         cudaFuncAttributeMaxDynamicSharedMemorySize, SMEM_BYTES);
    flash_attn_kernel<<<dim3(SEQ / BQ, BATCH * NH), 256, SMEM_BYTES>>>(Qp, Kp, Vp, Cp);

    gemm_nt_kernel<<<gg, 256>>>(Cp, Wo, out, MTOT, DM, DM);
}

// round 6
// speedup vs baseline: 1.3194x; 1.3194x over previous
#include <cuda_runtime.h>
#include <cuda_bf16.h>
#include <cstdint>
#include <math.h>

#define DM   1024
#define NH   16
#define HD   64
#define BATCH 2
#define SEQ  2048
#define MTOT (BATCH*SEQ)
#define K3   (3*DM)          // split-GEMM reduction dim: [hi, lo, hi] x [hi, hi, lo]
#define KC   64              // K elements per smem stage (64 bf16 = 128B rows)
#define NCHUNK (K3/KC)       // 48

// ---------------- scratch (__device__ globals: allocation-free rule) -------
__device__ float g_Q[MTOT*DM];
__device__ float g_K[MTOT*DM];
__device__ float g_V[MTOT*DM];
__device__ float g_C[MTOT*DM];
__device__ __nv_bfloat16 g_A2x[(size_t)MTOT*K3];   // split(x)
__device__ __nv_bfloat16 g_A2c[(size_t)MTOT*K3];   // split(ctx)
__device__ __nv_bfloat16 g_B2[4][(size_t)DM*K3];   // split(Wq,Wk,Wv,Wo)

// ---------------- PTX helpers (base sm_103-legal only) ---------------------
__device__ __forceinline__ uint32_t smem_u32(const void* p) {
    uint32_t a;
    asm("{ .reg .u64 t; cvta.to.shared.u64 t, %1; cvt.u32.u64 %0, t; }" : "=r"(a) : "l"(p));
    return a;
}
__device__ __forceinline__ void cp_async16(uint32_t dst, const void* src) {
    asm volatile("cp.async.cg.shared.global [%0], [%1], 16;\n" :: "r"(dst), "l"(src));
}
#define CP_COMMIT()  asm volatile("cp.async.commit_group;\n" ::: "memory")
#define CP_WAIT(n)   asm volatile("cp.async.wait_group %0;\n" :: "n"(n) : "memory")

__device__ __forceinline__ void ldsm_x4(uint32_t* r, uint32_t addr) {
    asm volatile("ldmatrix.sync.aligned.m8n8.x4.shared.b16 {%0,%1,%2,%3}, [%4];"
                 : "=r"(r[0]), "=r"(r[1]), "=r"(r[2]), "=r"(r[3]) : "r"(addr));
}
__device__ __forceinline__ void mma16816(float* d, const uint32_t* a,
                                         uint32_t b0, uint32_t b1) {
    asm volatile(
        "mma.sync.aligned.m16n8k16.row.col.f32.bf16.bf16.f32 "
        "{%0,%1,%2,%3}, {%4,%5,%6,%7}, {%8,%9}, {%0,%1,%2,%3};"
        : "+f"(d[0]), "+f"(d[1]), "+f"(d[2]), "+f"(d[3])
        : "r"(a[0]), "r"(a[1]), "r"(a[2]), "r"(a[3]), "r"(b0), "r"(b1));
}

// ---------------------------------------------------------------------------
// bf16 hi/lo split conversion. K fixed = 1024 (DM).
// act layout: [hi | lo | hi], weight layout: [hi | hi | lo]
// ---------------------------------------------------------------------------
__global__ void conv_split_act(const float* __restrict__ X, __nv_bfloat16* __restrict__ Y, int total) {
    int i = blockIdx.x * blockDim.x + threadIdx.x;
    if (i >= total) return;
    int r = i >> 10, k = i & 1023;
    float v = X[i];
    __nv_bfloat16 hi = __float2bfloat16_rn(v);
    __nv_bfloat16 lo = __float2bfloat16_rn(v - __bfloat162float(hi));
    size_t base = (size_t)r * K3 + k;
    Y[base]        = hi;
    Y[base + DM]   = lo;
    Y[base + 2*DM] = hi;
}
__global__ void conv_split_wt(const float* __restrict__ X, __nv_bfloat16* __restrict__ Y, int total) {
    int i = blockIdx.x * blockDim.x + threadIdx.x;
    if (i >= total) return;
    int r = i >> 10, k = i & 1023;
    float v = X[i];
    __nv_bfloat16 hi = __float2bfloat16_rn(v);
    __nv_bfloat16 lo = __float2bfloat16_rn(v - __bfloat162float(hi));
    size_t base = (size_t)r * K3 + k;
    Y[base]        = hi;
    Y[base + DM]   = hi;
    Y[base + 2*DM] = lo;
}

// ---------------------------------------------------------------------------
// HMMA NT-GEMM via mma.sync m16n8k16 bf16:
//   C[m][n] = sum_k A2[m][k] * B2[n][k]   (K = 3072 bf16, fp32 accum)
// CTA: 128x128, 256 threads (8 warps, each 32x64). BK=64 double-buffered
// cp.async. Rows are 128B -> xor-swizzle: chunk' = chunk ^ (row & 7),
// conflict-free for both the cp.async fill and the ldmatrix reads.
// ---------------------------------------------------------------------------
#define GEMM_SMEM 65536   // 2 stages x (16KB A + 16KB B)

__global__ __launch_bounds__(256) void gemm_mma_kernel(
    const __nv_bfloat16* __restrict__ A, const __nv_bfloat16* __restrict__ B,
    float* __restrict__ C)
{
    extern __shared__ char smem[];
    const uint32_t sbase = smem_u32(smem);

    const int tid  = threadIdx.x;
    const int wid  = tid >> 5;
    const int lane = tid & 31;
    const int wm   = wid & 3;        // warp m-tile (32 rows each)
    const int wn   = wid >> 2;       // warp n-tile (64 cols each)
    const int m0   = blockIdx.y * 128;
    const int n0   = blockIdx.x * 128;

    float acc[2][8][4];
#pragma unroll
    for (int i = 0; i < 2; i++)
#pragma unroll
        for (int j = 0; j < 8; j++)
#pragma unroll
            for (int v = 0; v < 4; v++) acc[i][j][v] = 0.0f;

    // ---- tile fill: 2048 x 16B cp.async per stage (8 per thread) ----
    auto fill = [&](int buf, int k0) {
#pragma unroll
        for (int i = 0; i < 8; i++) {
            int id  = tid + i * 256;          // 0..2047
            int isB = id >> 10;
            int rid = id & 1023;
            int row = rid >> 3;               // 0..127
            int cc  = rid & 7;                // 16B chunk in row
            const __nv_bfloat16* gp = (isB ? B + (size_t)(n0 + row) * K3
                                           : A + (size_t)(m0 + row) * K3) + k0 + cc * 8;
            uint32_t sw = (uint32_t)(row * 128 + ((cc ^ (row & 7)) * 16));
            cp_async16(sbase + buf * 32768 + isB * 16384 + sw, gp);
        }
    };

    const int lr = lane & 15;
    const int lc = lane >> 4;

    fill(0, 0);
    CP_COMMIT();

    for (int c = 0; c < NCHUNK; c++) {
        if (c + 1 < NCHUNK) { fill((c + 1) & 1, (c + 1) * KC); CP_COMMIT(); }
        if (c + 1 < NCHUNK) { CP_WAIT(1); } else { CP_WAIT(0); }
        __syncthreads();

        const uint32_t sA = sbase + (c & 1) * 32768;
        const uint32_t sB = sA + 16384;

#pragma unroll
        for (int ks = 0; ks < 4; ks++) {      // 4 x k16 per 64-K stage
            uint32_t a[2][4];
#pragma unroll
            for (int am = 0; am < 2; am++) {
                int row = wm * 32 + am * 16 + lr;
                int ch  = (ks * 2 + lc) ^ (row & 7);
                ldsm_x4(a[am], sA + row * 128 + ch * 16);
            }
            uint32_t b[4][4];
#pragma unroll
            for (int bn = 0; bn < 4; bn++) {
                int row = wn * 64 + bn * 16 + lr;
                int ch  = (ks * 2 + lc) ^ (row & 7);
                ldsm_x4(b[bn], sB + row * 128 + ch * 16);
            }
#pragma unroll
            for (int am = 0; am < 2; am++)
#pragma unroll
                for (int bn = 0; bn < 4; bn++) {
                    mma16816(acc[am][bn * 2 + 0], a[am], b[bn][0], b[bn][2]);
                    mma16816(acc[am][bn * 2 + 1], a[am], b[bn][1], b[bn][3]);
                }
        }
        __syncthreads();
    }

    // ---- epilogue: fragment -> global float2 stores ----
    const int erow = lane >> 2;
    const int ecol = (lane & 3) * 2;
#pragma unroll
    for (int am = 0; am < 2; am++) {
        int r0 = m0 + wm * 32 + am * 16 + erow;
#pragma unroll
        for (int bn = 0; bn < 8; bn++) {
            int col = n0 + wn * 64 + bn * 8 + ecol;
            *(float2*)&C[(size_t)r0 * DM + col] =
                make_float2(acc[am][bn][0], acc[am][bn][1]);
            *(float2*)&C[(size_t)(r0 + 8) * DM + col] =
                make_float2(acc[am][bn][2], acc[am][bn][3]);
        }
    }
}

// ---------------------------------------------------------------------------
// Flash attention (fp32, online softmax) — unchanged from passing R3 kernel
// ---------------------------------------------------------------------------
#define BQ   128
#define BKV  128
#define QP   (BQ + 4)
#define KP   (BKV + 4)
#define VP   (HD + 4)
#define PP   (BQ + 4)
#define SMEM_FLOATS (HD*QP + HD*KP + BKV*VP + BKV*PP)
#define SMEM_BYTES  (SMEM_FLOATS * 4)

__global__ __launch_bounds__(256) void flash_attn_kernel(
    const float* __restrict__ Q, const float* __restrict__ K,
    const float* __restrict__ V, float* __restrict__ O)
{
    extern __shared__ float sm[];
    float* Qt = sm;
    float* Kt = Qt + HD * QP;
    float* Vs = Kt + HD * KP;
    float* Pt = Vs + BKV * VP;

    const int tid = threadIdx.x;
    const int tr  = tid >> 4;
    const int tc  = tid & 15;
    const int bh  = blockIdx.y;
    const int b   = bh >> 4;
    const int h   = bh & 15;
    const int q0  = blockIdx.x * BQ;
    const long qbase = (long)(b * SEQ + q0);
    const long kvbase0 = (long)(b * SEQ);
    const int hb = h * HD;
    const float scale = 0.03125f;

    for (int idx = tid; idx < BQ * (HD / 4); idx += 256) {
        int row = idx >> 4;
        int c4  = (idx & 15) << 2;
        float4 v = *(const float4*)&Q[(qbase + row) * DM + hb + c4];
        Qt[(c4 + 0) * QP + row] = v.x;
        Qt[(c4 + 1) * QP + row] = v.y;
        Qt[(c4 + 2) * QP + row] = v.z;
        Qt[(c4 + 3) * QP + row] = v.w;
    }

    float m_i[8], l_i[8], o[8][4];
#pragma unroll
    for (int i = 0; i < 8; i++) {
        m_i[i] = -1e30f; l_i[i] = 0.0f;
#pragma unroll
        for (int c = 0; c < 4; c++) o[i][c] = 0.0f;
    }
    __syncthreads();

    for (int kb = 0; kb < SEQ / BKV; kb++) {
        const long kvr = kvbase0 + kb * BKV;
        for (int idx = tid; idx < BKV * (HD / 4); idx += 256) {
            int row = idx >> 4;
            int c4  = (idx & 15) << 2;
            float4 vk = *(const float4*)&K[(kvr + row) * DM + hb + c4];
            Kt[(c4 + 0) * KP + row] = vk.x;
            Kt[(c4 + 1) * KP + row] = vk.y;
            Kt[(c4 + 2) * KP + row] = vk.z;
            Kt[(c4 + 3) * KP + row] = vk.w;
            float4 vv = *(const float4*)&V[(kvr + row) * DM + hb + c4];
            *(float4*)&Vs[row * VP + c4] = vv;
        }
        __syncthreads();

        float s_[8][8];
#pragma unroll
        for (int i = 0; i < 8; i++)
#pragma unroll
            for (int j = 0; j < 8; j++) s_[i][j] = 0.0f;

#pragma unroll 4
        for (int k = 0; k < HD; k++) {
            float a[8], bq[8];
            *(float4*)&a[0]  = *(float4*)&Qt[k * QP + tr * 8];
            *(float4*)&a[4]  = *(float4*)&Qt[k * QP + tr * 8 + 4];
            *(float4*)&bq[0] = *(float4*)&Kt[k * KP + tc * 8];
            *(float4*)&bq[4] = *(float4*)&Kt[k * KP + tc * 8 + 4];
#pragma unroll
            for (int i = 0; i < 8; i++)
#pragma unroll
                for (int j = 0; j < 8; j++)
                    s_[i][j] += a[i] * bq[j];
        }

#pragma unroll
        for (int i = 0; i < 8; i++) {
            float rm = -1e30f;
#pragma unroll
            for (int j = 0; j < 8; j++) {
                s_[i][j] *= scale;
                rm = fmaxf(rm, s_[i][j]);
            }
#pragma unroll
            for (int off = 8; off >= 1; off >>= 1)
                rm = fmaxf(rm, __shfl_xor_sync(0xffffffffu, rm, off, 16));

            float m_new = fmaxf(m_i[i], rm);
            float corr  = __expf(m_i[i] - m_new);
            float rs = 0.0f;
#pragma unroll
            for (int j = 0; j < 8; j++) {
                float p = __expf(s_[i][j] - m_new);
                Pt[(tc * 8 + j) * PP + tr * 8 + i] = p;
                rs += p;
            }
#pragma unroll
            for (int off = 8; off >= 1; off >>= 1)
                rs += __shfl_xor_sync(0xffffffffu, rs, off, 16);

            l_i[i] = l_i[i] * corr + rs;
            m_i[i] = m_new;
#pragma unroll
            for (int c = 0; c < 4; c++) o[i][c] *= corr;
        }
        __syncthreads();

#pragma unroll 4
        for (int j = 0; j < BKV; j++) {
            float a[8];
            *(float4*)&a[0] = *(float4*)&Pt[j * PP + tr * 8];
            *(float4*)&a[4] = *(float4*)&Pt[j * PP + tr * 8 + 4];
            float4 bv = *(const float4*)&Vs[j * VP + tc * 4];
#pragma unroll
            for (int i = 0; i < 8; i++) {
                o[i][0] += a[i] * bv.x;
                o[i][1] += a[i] * bv.y;
                o[i][2] += a[i] * bv.z;
                o[i][3] += a[i] * bv.w;
            }
        }
        __syncthreads();
    }

#pragma unroll
    for (int i = 0; i < 8; i++) {
        float inv = 1.0f / l_i[i];
        float4 v = make_float4(o[i][0] * inv, o[i][1] * inv,
                               o[i][2] * inv, o[i][3] * inv);
        *(float4*)&O[(qbase + tr * 8 + i) * DM + hb + tc * 4] = v;
    }
}

// ---------------------------------------------------------------------------
extern "C" void kernel_launch(void* const* d_in, const int* in_sizes, int n_in,
                              void* d_out, int out_size)
{
    const float* x  = (const float*)d_in[0];
    const float* Wq = (const float*)d_in[1];
    const float* Wk = (const float*)d_in[2];
    const float* Wv = (const float*)d_in[3];
    const float* Wo = (const float*)d_in[4];
    float* out = (float*)d_out;

    float *Qp, *Kp, *Vp, *Cp;
    __nv_bfloat16 *A2x, *A2c, *B2;
    cudaGetSymbolAddress((void**)&Qp,  g_Q);
    cudaGetSymbolAddress((void**)&Kp,  g_K);
    cudaGetSymbolAddress((void**)&Vp,  g_V);
    cudaGetSymbolAddress((void**)&Cp,  g_C);
    cudaGetSymbolAddress((void**)&A2x, g_A2x);
    cudaGetSymbolAddress((void**)&A2c, g_A2c);
    cudaGetSymbolAddress((void**)&B2,  g_B2);

    static bool attr_done = false;
    if (!attr_done) {
        cudaFuncSetAttribute(gemm_mma_kernel,
                             cudaFuncAttributeMaxDynamicSharedMemorySize, GEMM_SMEM);
        cudaFuncSetAttribute(flash_attn_kernel,
                             cudaFuncAttributeMaxDynamicSharedMemorySize, SMEM_BYTES);
        attr_done = true;
    }

    const size_t WSTRIDE = (size_t)DM * K3;

    // 1) bf16 hi/lo splits
    conv_split_act<<<(MTOT * DM + 255) / 256, 256>>>(x, A2x, MTOT * DM);
    conv_split_wt <<<(DM * DM + 255) / 256, 256>>>(Wq, B2 + 0 * WSTRIDE, DM * DM);
    conv_split_wt <<<(DM * DM + 255) / 256, 256>>>(Wk, B2 + 1 * WSTRIDE, DM * DM);
    conv_split_wt <<<(DM * DM + 255) / 256, 256>>>(Wv, B2 + 2 * WSTRIDE, DM * DM);
    conv_split_wt <<<(DM * DM + 255) / 256, 256>>>(Wo, B2 + 3 * WSTRIDE, DM * DM);

    // 2) Q/K/V projections on tensor cores (HMMA)
    dim3 gg(DM / 128, MTOT / 128);   // (8, 32)
    gemm_mma_kernel<<<gg, 256, GEMM_SMEM>>>(A2x, B2 + 0 * WSTRIDE, Qp);
    gemm_mma_kernel<<<gg, 256, GEMM_SMEM>>>(A2x, B2 + 1 * WSTRIDE, Kp);
    gemm_mma_kernel<<<gg, 256, GEMM_SMEM>>>(A2x, B2 + 2 * WSTRIDE, Vp);

    // 3) attention (fp32)
    flash_attn_kernel<<<dim3(SEQ / BQ, BATCH * NH), 256, SMEM_BYTES>>>(Qp, Kp, Vp, Cp);

    // 4) output projection
    conv_split_act<<<(MTOT * DM + 255) / 256, 256>>>(Cp, A2c, MTOT * DM);
    gemm_mma_kernel<<<gg, 256, GEMM_SMEM>>>(A2c, B2 + 3 * WSTRIDE, out);
}

// round 7
// speedup vs baseline: 3.1096x; 2.3569x over previous
#include <cuda_runtime.h>
#include <cuda_bf16.h>
#include <cstdint>
#include <math.h>

#define DM    1024
#define NH    16
#define HD    64
#define BATCH 2
#define SEQ   2048
#define MTOT  (BATCH*SEQ)
#define K3    (3*DM)         // split-GEMM reduction dim: [hi, lo, hi] x [hi, hi, lo]
#define KC    64             // K elements per GEMM smem stage
#define NCHUNK (K3/KC)       // 48

// ---------------- scratch (__device__ globals: allocation-free rule) -------
// per-head split layouts: [b*NH+h][SEQ][HD]
#define PHN ((size_t)BATCH*NH*SEQ*HD)
__device__ __nv_bfloat16 g_Qh[PHN], g_Ql[PHN];
__device__ __nv_bfloat16 g_Kh[PHN], g_Kl[PHN];
__device__ __nv_bfloat16 g_Vh[PHN], g_Vl[PHN];
__device__ __nv_bfloat16 g_A2x[(size_t)MTOT*K3];   // split(x)
__device__ __nv_bfloat16 g_A2c[(size_t)MTOT*K3];   // split(ctx), written by attention
__device__ __nv_bfloat16 g_B2[4][(size_t)DM*K3];   // split(Wq,Wk,Wv,Wo)

// ---------------- PTX helpers (base sm_103-legal only) ---------------------
__device__ __forceinline__ uint32_t smem_u32(const void* p) {
    uint32_t a;
    asm("{ .reg .u64 t; cvta.to.shared.u64 t, %1; cvt.u32.u64 %0, t; }" : "=r"(a) : "l"(p));
    return a;
}
__device__ __forceinline__ void cp_async16(uint32_t dst, const void* src) {
    asm volatile("cp.async.cg.shared.global [%0], [%1], 16;\n" :: "r"(dst), "l"(src));
}
#define CP_COMMIT()  asm volatile("cp.async.commit_group;\n" ::: "memory")
#define CP_WAIT(n)   asm volatile("cp.async.wait_group %0;\n" :: "n"(n) : "memory")

__device__ __forceinline__ void ldsm_x4(uint32_t* r, uint32_t addr) {
    asm volatile("ldmatrix.sync.aligned.m8n8.x4.shared.b16 {%0,%1,%2,%3}, [%4];"
                 : "=r"(r[0]), "=r"(r[1]), "=r"(r[2]), "=r"(r[3]) : "r"(addr));
}
__device__ __forceinline__ void ldsm_x4_t(uint32_t* r, uint32_t addr) {
    asm volatile("ldmatrix.sync.aligned.m8n8.x4.trans.shared.b16 {%0,%1,%2,%3}, [%4];"
                 : "=r"(r[0]), "=r"(r[1]), "=r"(r[2]), "=r"(r[3]) : "r"(addr));
}
__device__ __forceinline__ void mma16816(float* d, const uint32_t* a,
                                         uint32_t b0, uint32_t b1) {
    asm volatile(
        "mma.sync.aligned.m16n8k16.row.col.f32.bf16.bf16.f32 "
        "{%0,%1,%2,%3}, {%4,%5,%6,%7}, {%8,%9}, {%0,%1,%2,%3};"
        : "+f"(d[0]), "+f"(d[1]), "+f"(d[2]), "+f"(d[3])
        : "r"(a[0]), "r"(a[1]), "r"(a[2]), "r"(a[3]), "r"(b0), "r"(b1));
}
__device__ __forceinline__ float ex2f(float x) {
    float y;
    asm("ex2.approx.ftz.f32 %0, %1;" : "=f"(y) : "f"(x));
    return y;
}
// (p0,p1) -> hi bf16x2 {lo=bf(p0), hi=bf(p1)} and lo bf16x2 residuals
__device__ __forceinline__ void split2(float p0, float p1, uint32_t& hi2, uint32_t& lo2) {
    asm("cvt.rn.bf16x2.f32 %0, %1, %2;" : "=r"(hi2) : "f"(p1), "f"(p0));
    float h0 = __uint_as_float(hi2 << 16);
    float h1 = __uint_as_float(hi2 & 0xffff0000u);
    float l0f = p0 - h0, l1f = p1 - h1;
    asm("cvt.rn.bf16x2.f32 %0, %1, %2;" : "=r"(lo2) : "f"(l1f), "f"(l0f));
}

// ---------------------------------------------------------------------------
// bf16 hi/lo split conversions (input-side only now)
// ---------------------------------------------------------------------------
__global__ void conv_split_act(const float* __restrict__ X, __nv_bfloat16* __restrict__ Y, int total) {
    int i = blockIdx.x * blockDim.x + threadIdx.x;
    if (i >= total) return;
    int r = i >> 10, k = i & 1023;
    float v = X[i];
    __nv_bfloat16 hi = __float2bfloat16_rn(v);
    __nv_bfloat16 lo = __float2bfloat16_rn(v - __bfloat162float(hi));
    size_t base = (size_t)r * K3 + k;
    Y[base]        = hi;
    Y[base + DM]   = lo;
    Y[base + 2*DM] = hi;
}
__global__ void conv_split_wt(const float* __restrict__ X, __nv_bfloat16* __restrict__ Y, int total) {
    int i = blockIdx.x * blockDim.x + threadIdx.x;
    if (i >= total) return;
    int r = i >> 10, k = i & 1023;
    float v = X[i];
    __nv_bfloat16 hi = __float2bfloat16_rn(v);
    __nv_bfloat16 lo = __float2bfloat16_rn(v - __bfloat162float(hi));
    size_t base = (size_t)r * K3 + k;
    Y[base]        = hi;
    Y[base + DM]   = hi;
    Y[base + 2*DM] = lo;
}

// ---------------------------------------------------------------------------
// HMMA NT-GEMM core (shared by both epilogues):
//   acc = sum_k A2[m][k]*B2[n][k], K=3072 bf16, fp32 acc, CTA 128x128, 8 warps
// ---------------------------------------------------------------------------
#define GEMM_SMEM 65536   // 2 stages x (16KB A + 16KB B)

struct GemmCore {
    float acc[2][8][4];
    int wm, wn, m0, n0, lane;
};

__device__ __forceinline__ void gemm_core_run(
    GemmCore& G, char* smem,
    const __nv_bfloat16* __restrict__ A, const __nv_bfloat16* __restrict__ B)
{
    const uint32_t sbase = smem_u32(smem);
    const int tid  = threadIdx.x;
    const int wid  = tid >> 5;
    G.lane = tid & 31;
    G.wm   = wid & 3;
    G.wn   = wid >> 2;
    G.m0   = blockIdx.y * 128;
    G.n0   = blockIdx.x * 128;

#pragma unroll
    for (int i = 0; i < 2; i++)
#pragma unroll
        for (int j = 0; j < 8; j++)
#pragma unroll
            for (int v = 0; v < 4; v++) G.acc[i][j][v] = 0.0f;

    auto fill = [&](int buf, int k0) {
#pragma unroll
        for (int i = 0; i < 8; i++) {
            int id  = tid + i * 256;
            int isB = id >> 10;
            int rid = id & 1023;
            int row = rid >> 3;
            int cc  = rid & 7;
            const __nv_bfloat16* gp = (isB ? B + (size_t)(G.n0 + row) * K3
                                           : A + (size_t)(G.m0 + row) * K3) + k0 + cc * 8;
            uint32_t sw = (uint32_t)(row * 128 + ((cc ^ (row & 7)) * 16));
            cp_async16(sbase + buf * 32768 + isB * 16384 + sw, gp);
        }
    };

    const int lr = G.lane & 15;
    const int lc = G.lane >> 4;

    fill(0, 0);
    CP_COMMIT();

    for (int c = 0; c < NCHUNK; c++) {
        if (c + 1 < NCHUNK) { fill((c + 1) & 1, (c + 1) * KC); CP_COMMIT(); CP_WAIT(1); }
        else                { CP_WAIT(0); }
        __syncthreads();

        const uint32_t sA = sbase + (c & 1) * 32768;
        const uint32_t sB = sA + 16384;

#pragma unroll
        for (int ks = 0; ks < 4; ks++) {
            uint32_t a[2][4];
#pragma unroll
            for (int am = 0; am < 2; am++) {
                int row = G.wm * 32 + am * 16 + lr;
                int ch  = (ks * 2 + lc) ^ (row & 7);
                ldsm_x4(a[am], sA + row * 128 + ch * 16);
            }
            uint32_t b[4][4];
#pragma unroll
            for (int bn = 0; bn < 4; bn++) {
                int row = G.wn * 64 + bn * 16 + lr;
                int ch  = (ks * 2 + lc) ^ (row & 7);
                ldsm_x4(b[bn], sB + row * 128 + ch * 16);
            }
#pragma unroll
            for (int am = 0; am < 2; am++)
#pragma unroll
                for (int bn = 0; bn < 4; bn++) {
                    mma16816(G.acc[am][bn * 2 + 0], a[am], b[bn][0], b[bn][2]);
                    mma16816(G.acc[am][bn * 2 + 1], a[am], b[bn][1], b[bn][3]);
                }
        }
        __syncthreads();
    }
}

// epilogue A: plain fp32 output (Wo projection)
__global__ __launch_bounds__(256) void gemm_mma_kernel(
    const __nv_bfloat16* __restrict__ A, const __nv_bfloat16* __restrict__ B,
    float* __restrict__ C)
{
    extern __shared__ char smem[];
    GemmCore G;
    gemm_core_run(G, smem, A, B);

    const int erow = G.lane >> 2;
    const int ecol = (G.lane & 3) * 2;
#pragma unroll
    for (int am = 0; am < 2; am++) {
        int r0 = G.m0 + G.wm * 32 + am * 16 + erow;
#pragma unroll
        for (int bn = 0; bn < 8; bn++) {
            int col = G.n0 + G.wn * 64 + bn * 8 + ecol;
            *(float2*)&C[(size_t)r0 * DM + col] =
                make_float2(G.acc[am][bn][0], G.acc[am][bn][1]);
            *(float2*)&C[(size_t)(r0 + 8) * DM + col] =
                make_float2(G.acc[am][bn][2], G.acc[am][bn][3]);
        }
    }
}

// epilogue B: split-bf16 per-head output (Q/K/V projections)
__global__ __launch_bounds__(256) void gemm_mma_split_kernel(
    const __nv_bfloat16* __restrict__ A, const __nv_bfloat16* __restrict__ B,
    __nv_bfloat16* __restrict__ Hi, __nv_bfloat16* __restrict__ Lo)
{
    extern __shared__ char smem[];
    GemmCore G;
    gemm_core_run(G, smem, A, B);

    const int erow = G.lane >> 2;
    const int ecol = (G.lane & 3) * 2;
#pragma unroll
    for (int am = 0; am < 2; am++) {
        int rbase = G.m0 + G.wm * 32 + am * 16 + erow;
#pragma unroll
        for (int bn = 0; bn < 8; bn++) {
            int col = G.n0 + G.wn * 64 + bn * 8 + ecol;
            int h = col >> 6, d = col & 63;
#pragma unroll
            for (int half = 0; half < 2; half++) {
                int r = rbase + half * 8;
                float v0 = G.acc[am][bn][half * 2 + 0];
                float v1 = G.acc[am][bn][half * 2 + 1];
                uint32_t hi2, lo2;
                split2(v0, v1, hi2, lo2);
                size_t idx = ((size_t)((r >> 11) * NH + h) * SEQ + (r & 2047)) * HD + d;
                *(uint32_t*)(Hi + idx) = hi2;
                *(uint32_t*)(Lo + idx) = lo2;
            }
        }
    }
}

// ---------------------------------------------------------------------------
// Tensor-core flash attention.
// Grid: (SEQ/128, BATCH*NH). 256 threads = 8 warps, warp w owns q rows [16w,16w+16).
// S = Qhi*Khi + Qlo*Khi + Qhi*Klo ; online softmax fp32 ;
// P split to bf16 hi/lo in-register ; O += Phi*Vhi + Plo*Vhi + Phi*Vlo.
// Writes ctx directly in [hi|lo|hi] split layout for the Wo GEMM.
// ---------------------------------------------------------------------------
#define ATT_SMEM (2*16384 + 2*65536)   // Qhi,Qlo + 2 KV stages (Kh,Kl,Vh,Vl)

__global__ __launch_bounds__(256) void attn_mma_kernel(
    __nv_bfloat16* __restrict__ A2c)
{
    extern __shared__ char smem[];
    const uint32_t sb  = smem_u32(smem);
    const uint32_t sQh = sb, sQl = sb + 16384;
    const uint32_t sKV = sb + 32768;            // + stage*65536 ; tiles: Kh,Kl,Vh,Vl @ t*16384

    const int tid  = threadIdx.x;
    const int w    = tid >> 5;
    const int lane = tid & 31;
    const int bh   = blockIdx.y;                // b*NH + h
    const int b    = bh >> 4;
    const int h    = bh & 15;
    const int q0   = blockIdx.x * 128;

    const __nv_bfloat16* Qh = g_Qh + (size_t)bh * SEQ * HD;
    const __nv_bfloat16* Ql = g_Ql + (size_t)bh * SEQ * HD;
    const __nv_bfloat16* Kh = g_Kh + (size_t)bh * SEQ * HD;
    const __nv_bfloat16* Kl = g_Kl + (size_t)bh * SEQ * HD;
    const __nv_bfloat16* Vh = g_Vh + (size_t)bh * SEQ * HD;
    const __nv_bfloat16* Vl = g_Vl + (size_t)bh * SEQ * HD;

    // ---- fill Q tiles (hi, lo) ----
#pragma unroll
    for (int i = 0; i < 8; i++) {
        int id  = tid + i * 256;                // 0..2047
        int t   = id >> 10;                     // 0: Qh, 1: Ql
        int rid = id & 1023;
        int row = rid >> 3;
        int cc  = rid & 7;
        const __nv_bfloat16* gp = (t ? Ql : Qh) + (size_t)(q0 + row) * HD + cc * 8;
        uint32_t sw = (uint32_t)(row * 128 + ((cc ^ (row & 7)) * 16));
        cp_async16((t ? sQl : sQh) + sw, gp);
    }
    auto fill_kv = [&](int stage, int kv0) {
#pragma unroll
        for (int i = 0; i < 16; i++) {
            int id  = tid + i * 256;            // 0..4095
            int t   = id >> 10;                 // 0:Kh 1:Kl 2:Vh 3:Vl
            int rid = id & 1023;
            int row = rid >> 3;
            int cc  = rid & 7;
            const __nv_bfloat16* base = (t == 0) ? Kh : (t == 1) ? Kl : (t == 2) ? Vh : Vl;
            const __nv_bfloat16* gp = base + (size_t)(kv0 + row) * HD + cc * 8;
            uint32_t sw = (uint32_t)(row * 128 + ((cc ^ (row & 7)) * 16));
            cp_async16(sKV + stage * 65536 + t * 16384 + sw, gp);
        }
    };
    fill_kv(0, 0);
    CP_COMMIT();

    const int lr = lane & 15;
    const int lc = lane >> 4;
    const int g  = lane >> 2;
    const int t4 = lane & 3;
    const float CS = 0.045084437562f;           // (1/32) * log2(e)

    float m0 = -1e30f, m1 = -1e30f, l0 = 0.0f, l1 = 0.0f;
    float o[8][4];
#pragma unroll
    for (int j = 0; j < 8; j++)
#pragma unroll
        for (int v = 0; v < 4; v++) o[j][v] = 0.0f;

    for (int kb = 0; kb < SEQ / 128; kb++) {
        if (kb + 1 < SEQ / 128) { fill_kv((kb + 1) & 1, (kb + 1) * 128); CP_COMMIT(); CP_WAIT(1); }
        else                    { CP_WAIT(0); }
        __syncthreads();

        const uint32_t stg = sKV + (kb & 1) * 65536;

        // ---- S = QK^T (3 split passes fused per nb) ----
        float s[16][4];
#pragma unroll
        for (int j = 0; j < 16; j++)
#pragma unroll
            for (int v = 0; v < 4; v++) s[j][v] = 0.0f;

#pragma unroll
        for (int ks = 0; ks < 4; ks++) {
            uint32_t aQh[4], aQl[4];
            {
                int row = w * 16 + lr;
                uint32_t off = (uint32_t)(row * 128 + (((ks * 2 + lc) ^ (row & 7)) * 16));
                ldsm_x4(aQh, sQh + off);
                ldsm_x4(aQl, sQl + off);
            }
#pragma unroll
            for (int nb = 0; nb < 8; nb++) {
                int row = nb * 16 + lr;
                uint32_t off = (uint32_t)(row * 128 + (((ks * 2 + lc) ^ (row & 7)) * 16));
                uint32_t bh_[4], bl_[4];
                ldsm_x4(bh_, stg + off);               // Khi
                mma16816(s[nb * 2 + 0], aQh, bh_[0], bh_[2]);
                mma16816(s[nb * 2 + 1], aQh, bh_[1], bh_[3]);
                mma16816(s[nb * 2 + 0], aQl, bh_[0], bh_[2]);
                mma16816(s[nb * 2 + 1], aQl, bh_[1], bh_[3]);
                ldsm_x4(bl_, stg + 16384 + off);       // Klo
                mma16816(s[nb * 2 + 0], aQh, bl_[0], bl_[2]);
                mma16816(s[nb * 2 + 1], aQh, bl_[1], bl_[3]);
            }
        }

        // ---- online softmax (base-2), rows g and g+8 ----
        float rm0 = -1e30f, rm1 = -1e30f;
#pragma unroll
        for (int j = 0; j < 16; j++) {
            s[j][0] *= CS; s[j][1] *= CS; s[j][2] *= CS; s[j][3] *= CS;
            rm0 = fmaxf(rm0, fmaxf(s[j][0], s[j][1]));
            rm1 = fmaxf(rm1, fmaxf(s[j][2], s[j][3]));
        }
        rm0 = fmaxf(rm0, __shfl_xor_sync(0xffffffffu, rm0, 1));
        rm0 = fmaxf(rm0, __shfl_xor_sync(0xffffffffu, rm0, 2));
        rm1 = fmaxf(rm1, __shfl_xor_sync(0xffffffffu, rm1, 1));
        rm1 = fmaxf(rm1, __shfl_xor_sync(0xffffffffu, rm1, 2));

        float mn0 = fmaxf(m0, rm0), mn1 = fmaxf(m1, rm1);
        float c0 = ex2f(m0 - mn0),  c1 = ex2f(m1 - mn1);
        m0 = mn0; m1 = mn1;

        float rs0 = 0.0f, rs1 = 0.0f;
#pragma unroll
        for (int j = 0; j < 16; j++) {
            s[j][0] = ex2f(s[j][0] - mn0);
            s[j][1] = ex2f(s[j][1] - mn0);
            s[j][2] = ex2f(s[j][2] - mn1);
            s[j][3] = ex2f(s[j][3] - mn1);
            rs0 += s[j][0] + s[j][1];
            rs1 += s[j][2] + s[j][3];
        }
        rs0 += __shfl_xor_sync(0xffffffffu, rs0, 1);
        rs0 += __shfl_xor_sync(0xffffffffu, rs0, 2);
        rs1 += __shfl_xor_sync(0xffffffffu, rs1, 1);
        rs1 += __shfl_xor_sync(0xffffffffu, rs1, 2);
        l0 = l0 * c0 + rs0;
        l1 = l1 * c1 + rs1;
#pragma unroll
        for (int j = 0; j < 8; j++) {
            o[j][0] *= c0; o[j][1] *= c0; o[j][2] *= c1; o[j][3] *= c1;
        }

        // ---- O += P V (P from S frags, 3 split passes) ----
        const int vtile = lane >> 3;
        const int vrit  = lane & 7;
#pragma unroll
        for (int kk = 0; kk < 8; kk++) {
            uint32_t ah[4], al[4];
            split2(s[2 * kk + 0][0], s[2 * kk + 0][1], ah[0], al[0]);
            split2(s[2 * kk + 0][2], s[2 * kk + 0][3], ah[1], al[1]);
            split2(s[2 * kk + 1][0], s[2 * kk + 1][1], ah[2], al[2]);
            split2(s[2 * kk + 1][2], s[2 * kk + 1][3], ah[3], al[3]);
#pragma unroll
            for (int nb = 0; nb < 4; nb++) {
                int kvrow = kk * 16 + (vtile & 1) * 8 + vrit;
                int ch    = nb * 2 + (vtile >> 1);
                uint32_t off = (uint32_t)(kvrow * 128 + ((ch ^ (kvrow & 7)) * 16));
                uint32_t vh_[4], vl_[4];
                ldsm_x4_t(vh_, stg + 32768 + off);     // Vhi
                mma16816(o[nb * 2 + 0], ah, vh_[0], vh_[1]);
                mma16816(o[nb * 2 + 1], ah, vh_[2], vh_[3]);
                mma16816(o[nb * 2 + 0], al, vh_[0], vh_[1]);
                mma16816(o[nb * 2 + 1], al, vh_[2], vh_[3]);
                ldsm_x4_t(vl_, stg + 49152 + off);     // Vlo
                mma16816(o[nb * 2 + 0], ah, vl_[0], vl_[1]);
                mma16816(o[nb * 2 + 1], ah, vl_[2], vl_[3]);
            }
        }
        __syncthreads();
    }

    // ---- epilogue: normalize, split, write [hi|lo|hi] for Wo GEMM ----
    float i0 = 1.0f / l0, i1 = 1.0f / l1;
    int tok0 = b * SEQ + q0 + w * 16 + g;
    int tok1 = tok0 + 8;
#pragma unroll
    for (int nb = 0; nb < 8; nb++) {
        int col = h * HD + nb * 8 + t4 * 2;
        uint32_t hi2, lo2;
        split2(o[nb][0] * i0, o[nb][1] * i0, hi2, lo2);
        __nv_bfloat16* p = A2c + (size_t)tok0 * K3 + col;
        *(uint32_t*)(p)          = hi2;
        *(uint32_t*)(p + DM)     = lo2;
        *(uint32_t*)(p + 2 * DM) = hi2;
        split2(o[nb][2] * i1, o[nb][3] * i1, hi2, lo2);
        p = A2c + (size_t)tok1 * K3 + col;
        *(uint32_t*)(p)          = hi2;
        *(uint32_t*)(p + DM)     = lo2;
        *(uint32_t*)(p + 2 * DM) = hi2;
    }
}

// ---------------------------------------------------------------------------
extern "C" void kernel_launch(void* const* d_in, const int* in_sizes, int n_in,
                              void* d_out, int out_size)
{
    const float* x  = (const float*)d_in[0];
    const float* Wq = (const float*)d_in[1];
    const float* Wk = (const float*)d_in[2];
    const float* Wv = (const float*)d_in[3];
    const float* Wo = (const float*)d_in[4];
    float* out = (float*)d_out;

    __nv_bfloat16 *A2x, *A2c, *B2;
    __nv_bfloat16 *Qh, *Ql, *Kh, *Kl, *Vh, *Vl;
    cudaGetSymbolAddress((void**)&A2x, g_A2x);
    cudaGetSymbolAddress((void**)&A2c, g_A2c);
    cudaGetSymbolAddress((void**)&B2,  g_B2);
    cudaGetSymbolAddress((void**)&Qh,  g_Qh);
    cudaGetSymbolAddress((void**)&Ql,  g_Ql);
    cudaGetSymbolAddress((void**)&Kh,  g_Kh);
    cudaGetSymbolAddress((void**)&Kl,  g_Kl);
    cudaGetSymbolAddress((void**)&Vh,  g_Vh);
    cudaGetSymbolAddress((void**)&Vl,  g_Vl);

    static bool attr_done = false;
    if (!attr_done) {
        cudaFuncSetAttribute(gemm_mma_kernel,
                             cudaFuncAttributeMaxDynamicSharedMemorySize, GEMM_SMEM);
        cudaFuncSetAttribute(gemm_mma_split_kernel,
                             cudaFuncAttributeMaxDynamicSharedMemorySize, GEMM_SMEM);
        cudaFuncSetAttribute(attn_mma_kernel,
                             cudaFuncAttributeMaxDynamicSharedMemorySize, ATT_SMEM);
        attr_done = true;
    }

    const size_t WSTRIDE = (size_t)DM * K3;

    // 1) bf16 hi/lo splits of inputs
    conv_split_act<<<(MTOT * DM + 255) / 256, 256>>>(x, A2x, MTOT * DM);
    conv_split_wt <<<(DM * DM + 255) / 256, 256>>>(Wq, B2 + 0 * WSTRIDE, DM * DM);
    conv_split_wt <<<(DM * DM + 255) / 256, 256>>>(Wk, B2 + 1 * WSTRIDE, DM * DM);
    conv_split_wt <<<(DM * DM + 255) / 256, 256>>>(Wv, B2 + 2 * WSTRIDE, DM * DM);
    conv_split_wt <<<(DM * DM + 255) / 256, 256>>>(Wo, B2 + 3 * WSTRIDE, DM * DM);

    // 2) Q/K/V projections -> split per-head layouts directly
    dim3 gg(DM / 128, MTOT / 128);   // (8, 32)
    gemm_mma_split_kernel<<<gg, 256, GEMM_SMEM>>>(A2x, B2 + 0 * WSTRIDE, Qh, Ql);
    gemm_mma_split_kernel<<<gg, 256, GEMM_SMEM>>>(A2x, B2 + 1 * WSTRIDE, Kh, Kl);
    gemm_mma_split_kernel<<<gg, 256, GEMM_SMEM>>>(A2x, B2 + 2 * WSTRIDE, Vh, Vl);

    // 3) tensor-core flash attention -> split ctx
    attn_mma_kernel<<<dim3(SEQ / 128, BATCH * NH), 256, ATT_SMEM>>>(A2c);

    // 4) output projection
    gemm_mma_kernel<<<gg, 256, GEMM_SMEM>>>(A2c, B2 + 3 * WSTRIDE, out);
}